// round 1
// baseline (speedup 1.0000x reference)
#include <cuda_runtime.h>

// SurfEval: NURBS surface evaluation.
// B=8 (derived), M=N=64, P=Q=3, GRID=512, DIM=3.
// out[b,g,h,:] = (sum_{r,s} Nu[g,r] Nv[h,s] ctrl[b, us[g]-3+r, vs[h]-3+s, 0:3..]) homogeneous-divided.
//
// Block = (g, b). Stage A builds the u-contracted row Su[n] (64 x float4) in smem.
// Stage B: each of 128 threads evaluates 4 consecutive h points and writes
// 48 bytes as three aligned float4 stores.

#define GRID_N 512
#define MCTRL 64
#define NCTRL 64

__global__ __launch_bounds__(128) void surf_eval_kernel(
    const float4* __restrict__ ctrl,   // (B, 64, 64) float4
    const int*    __restrict__ uspan,  // (512)
    const int4*   __restrict__ vspan4, // (512) ints viewed as (128) int4
    const float4* __restrict__ Nu,     // (512) float4
    const float4* __restrict__ Nv,     // (512) float4
    float4*       __restrict__ out)    // (B*512*512*3)/4 float4
{
    __shared__ float4 Su[NCTRL];

    const int g = blockIdx.x;
    const int b = blockIdx.y;
    const int t = threadIdx.x;

    // ---- Stage A: Su[n] = sum_r Nu[g,r] * ctrl[b, us-3+r, n, :] ----
    if (t < NCTRL) {
        const int us = __ldg(uspan + g);
        const float4 nu = __ldg(Nu + g);
        const float4* base = ctrl + ((size_t)b * MCTRL + (size_t)(us - 3)) * NCTRL + t;
        const float4 c0 = __ldg(base);
        const float4 c1 = __ldg(base + NCTRL);
        const float4 c2 = __ldg(base + 2 * NCTRL);
        const float4 c3 = __ldg(base + 3 * NCTRL);
        float4 a;
        a.x = nu.x * c0.x + nu.y * c1.x + nu.z * c2.x + nu.w * c3.x;
        a.y = nu.x * c0.y + nu.y * c1.y + nu.z * c2.y + nu.w * c3.y;
        a.z = nu.x * c0.z + nu.y * c1.z + nu.z * c2.z + nu.w * c3.z;
        a.w = nu.x * c0.w + nu.y * c1.w + nu.z * c2.w + nu.w * c3.w;
        Su[t] = a;
    }
    __syncthreads();

    // ---- Stage B: 4 consecutive h points per thread ----
    const int h0 = t << 2;
    const int4 vsv = __ldg(vspan4 + t);
    const int vs[4] = {vsv.x, vsv.y, vsv.z, vsv.w};

    float r[12];
#pragma unroll
    for (int k = 0; k < 4; ++k) {
        const float4 nv = __ldg(Nv + h0 + k);
        const int j = vs[k] - 3;
        const float4 s0 = Su[j];
        const float4 s1 = Su[j + 1];
        const float4 s2 = Su[j + 2];
        const float4 s3 = Su[j + 3];
        const float X = nv.x * s0.x + nv.y * s1.x + nv.z * s2.x + nv.w * s3.x;
        const float Y = nv.x * s0.y + nv.y * s1.y + nv.z * s2.y + nv.w * s3.y;
        const float Z = nv.x * s0.z + nv.y * s1.z + nv.z * s2.z + nv.w * s3.z;
        const float W = nv.x * s0.w + nv.y * s1.w + nv.z * s2.w + nv.w * s3.w;
        const float inv = __fdividef(1.0f, W);
        r[k * 3 + 0] = X * inv;
        r[k * 3 + 1] = Y * inv;
        r[k * 3 + 2] = Z * inv;
    }

    // out row (b,g) is 512*3 floats = 384 float4, aligned. Thread writes float4 [3t, 3t+2].
    float4* o = out + ((size_t)(b * GRID_N + g) * GRID_N * 3) / 4 + (size_t)t * 3;
    o[0] = make_float4(r[0], r[1], r[2], r[3]);
    o[1] = make_float4(r[4], r[5], r[6], r[7]);
    o[2] = make_float4(r[8], r[9], r[10], r[11]);
}

extern "C" void kernel_launch(void* const* d_in, const int* in_sizes, int n_in,
                              void* d_out, int out_size) {
    const float4* ctrl   = (const float4*)d_in[0];
    const int*    uspan  = (const int*)d_in[1];
    const int4*   vspan4 = (const int4*)d_in[2];
    const float4* Nu     = (const float4*)d_in[3];
    const float4* Nv     = (const float4*)d_in[4];

    const int B = in_sizes[0] / (MCTRL * NCTRL * 4);  // ctrl_pts elements = B*64*64*4

    dim3 grid(GRID_N, B);
    surf_eval_kernel<<<grid, 128>>>(ctrl, uspan, vspan4, Nu, Nv, (float4*)d_out);
}

// round 2
// speedup vs baseline: 1.1429x; 1.1429x over previous
#include <cuda_runtime.h>

// SurfEval: NURBS surface evaluation. B=8, M=N=64, P=Q=3, GRID=512, DIM=3.
// Block = (g, b). Stage A: u-contracted row Su[n] (64 x float4) in smem.
// Stage B: each thread evaluates 4 consecutive h points using ONE 5-wide
// Su window (5 LDS.128 instead of 16) + span-delta-shifted Nv weights,
// then writes 48B as three aligned float4 stores.

#define GRID_N 512
#define MCTRL 64
#define NCTRL 64

__global__ __launch_bounds__(128) void surf_eval_kernel(
    const float4* __restrict__ ctrl,   // (B, 64, 64) float4
    const int*    __restrict__ uspan,  // (512)
    const int4*   __restrict__ vspan4, // (512) ints viewed as (128) int4
    const float4* __restrict__ Nu,     // (512) float4
    const float4* __restrict__ Nv,     // (512) float4
    float4*       __restrict__ out)    // (B*512*512*3)/4 float4
{
    __shared__ float4 Su[NCTRL + 1];   // +1: q-window may touch index 64 (zeroed)

    const int g = blockIdx.x;
    const int b = blockIdx.y;
    const int t = threadIdx.x;

    // ---- Stage A: Su[n] = sum_r Nu[g,r] * ctrl[b, us-3+r, n, :] ----
    if (t < NCTRL) {
        const int us = __ldg(uspan + g);
        const float4 nu = __ldg(Nu + g);
        const float4* base = ctrl + ((size_t)b * MCTRL + (size_t)(us - 3)) * NCTRL + t;
        const float4 c0 = __ldg(base);
        const float4 c1 = __ldg(base + NCTRL);
        const float4 c2 = __ldg(base + 2 * NCTRL);
        const float4 c3 = __ldg(base + 3 * NCTRL);
        float4 a;
        a.x = nu.x * c0.x + nu.y * c1.x + nu.z * c2.x + nu.w * c3.x;
        a.y = nu.x * c0.y + nu.y * c1.y + nu.z * c2.y + nu.w * c3.y;
        a.z = nu.x * c0.z + nu.y * c1.z + nu.z * c2.z + nu.w * c3.z;
        a.w = nu.x * c0.w + nu.y * c1.w + nu.z * c2.w + nu.w * c3.w;
        Su[t] = a;
    } else if (t == NCTRL) {
        Su[NCTRL] = make_float4(0.f, 0.f, 0.f, 0.f);
    }
    __syncthreads();

    // ---- Stage B: 4 consecutive h points per thread, one 5-wide Su window ----
    const int h0 = t << 2;
    const int4 vsv = __ldg(vspan4 + t);
    const int vs_arr[4] = {vsv.x, vsv.y, vsv.z, vsv.w};
    const int j0 = vsv.x - 3;

    float4 q0 = Su[j0];
    float4 q1 = Su[j0 + 1];
    float4 q2 = Su[j0 + 2];
    float4 q3 = Su[j0 + 3];
    float4 q4 = Su[j0 + 4];

    float r[12];
#pragma unroll
    for (int k = 0; k < 4; ++k) {
        const float4 nv = __ldg(Nv + h0 + k);
        const bool s = (vs_arr[k] != vsv.x);   // span delta (0 or 1, guaranteed)
        const float w0 = s ? 0.0f : nv.x;
        const float w1 = s ? nv.x : nv.y;
        const float w2 = s ? nv.y : nv.z;
        const float w3 = s ? nv.z : nv.w;
        const float w4 = s ? nv.w : 0.0f;

        const float X = w0 * q0.x + w1 * q1.x + w2 * q2.x + w3 * q3.x + w4 * q4.x;
        const float Y = w0 * q0.y + w1 * q1.y + w2 * q2.y + w3 * q3.y + w4 * q4.y;
        const float Z = w0 * q0.z + w1 * q1.z + w2 * q2.z + w3 * q3.z + w4 * q4.z;
        const float W = w0 * q0.w + w1 * q1.w + w2 * q2.w + w3 * q3.w + w4 * q4.w;

        const float inv = __fdividef(1.0f, W);
        r[k * 3 + 0] = X * inv;
        r[k * 3 + 1] = Y * inv;
        r[k * 3 + 2] = Z * inv;
    }

    // out row (b,g) is 512*3 floats = 384 float4, aligned. Thread writes float4 [3t, 3t+2].
    float4* o = out + ((size_t)(b * GRID_N + g) * GRID_N * 3) / 4 + (size_t)t * 3;
    o[0] = make_float4(r[0], r[1], r[2], r[3]);
    o[1] = make_float4(r[4], r[5], r[6], r[7]);
    o[2] = make_float4(r[8], r[9], r[10], r[11]);
}

extern "C" void kernel_launch(void* const* d_in, const int* in_sizes, int n_in,
                              void* d_out, int out_size) {
    const float4* ctrl   = (const float4*)d_in[0];
    const int*    uspan  = (const int*)d_in[1];
    const int4*   vspan4 = (const int4*)d_in[2];
    const float4* Nu     = (const float4*)d_in[3];
    const float4* Nv     = (const float4*)d_in[4];

    const int B = in_sizes[0] / (MCTRL * NCTRL * 4);  // ctrl_pts elements = B*64*64*4

    dim3 grid(GRID_N, B);
    surf_eval_kernel<<<grid, 128>>>(ctrl, uspan, vspan4, Nu, Nv, (float4*)d_out);
}